// round 2
// baseline (speedup 1.0000x reference)
#include <cuda_runtime.h>

#define DIN 128
#define HID 16
#define NMAX 100000

// ---------------- device scratch (static; no runtime allocation) ----------------
__device__ __align__(16) float g_hp[NMAX * HID];
__device__ __align__(16) float g_ht[NMAX * HID];

// per-node attention dot products, one pair per edge type
__device__ float g_a_pt_src[NMAX], g_a_pt_dst[NMAX];
__device__ float g_a_tt_src[NMAX], g_a_tt_dst[NMAX];
__device__ float g_a_tp_src[NMAX], g_a_tp_dst[NMAX];
__device__ float g_a_pp_src[NMAX], g_a_pp_dst[NMAX];

// softmax denominators per edge type (unshifted)
__device__ float g_s_pt[NMAX], g_s_tt[NMAX], g_s_tp[NMAX], g_s_pp[NMAX];

// UN-normalized aggregation outputs per edge type
__device__ __align__(16) float g_out_pt[NMAX * HID];
__device__ __align__(16) float g_out_tt[NMAX * HID];
__device__ __align__(16) float g_out_tp[NMAX * HID];
__device__ __align__(16) float g_out_pp[NMAX * HID];

// semantic-attention accumulators
__device__ float g_S_p[2 * HID];
__device__ float g_S_t[2 * HID];
__device__ float g_attn[4];     // [attn_p0, attn_p1, attn_t0, attn_t1]
__device__ float g_pooled[HID];

// ---------------- helpers ----------------
__device__ __forceinline__ void red_add_v4(float* addr, float a, float b, float c, float d) {
    asm volatile("red.global.add.v4.f32 [%0], {%1, %2, %3, %4};"
                 :: "l"(addr), "f"(a), "f"(b), "f"(c), "f"(d) : "memory");
}
__device__ __forceinline__ void red_add_f32(float* addr, float v) {
    asm volatile("red.global.add.f32 [%0], %1;" :: "l"(addr), "f"(v) : "memory");
}

// ---------------- zero scratch ----------------
__global__ void zero_kernel(int n) {
    int i = blockIdx.x * blockDim.x + threadIdx.x;
    int n16 = n * HID;
    if (i < n16) {
        g_out_pt[i] = 0.f; g_out_tt[i] = 0.f; g_out_tp[i] = 0.f; g_out_pp[i] = 0.f;
    }
    if (i < n) {
        g_s_pt[i] = 0.f; g_s_tt[i] = 0.f; g_s_tp[i] = 0.f; g_s_pp[i] = 0.f;
    }
    if (i < 2 * HID) { g_S_p[i] = 0.f; g_S_t[i] = 0.f; }
    if (i < HID) g_pooled[i] = 0.f;
}

// ---------------- projection: h = x @ W + b ----------------
// 256 threads, 64 nodes/block, 4 threads per node (4 outputs each)
__global__ __launch_bounds__(256) void proj_kernel(
    const float* __restrict__ x, const float* __restrict__ w,
    const float* __restrict__ b, int which, int n)
{
    __shared__ float xs[64][DIN + 4];   // +4 pad: bank = (ni*4 + j) % 32, conflict-free
    __shared__ float ws[DIN][HID];
    __shared__ float bs[HID];
    int tid = threadIdx.x;
    for (int idx = tid; idx < DIN * HID; idx += 256)
        ws[idx / HID][idx % HID] = w[idx];
    if (tid < HID) bs[tid] = b[tid];
    int base = blockIdx.x * 64;
    for (int l = tid; l < 64 * DIN; l += 256) {
        int node = l / DIN, j = l % DIN;
        xs[node][j] = (base + node < n) ? x[(size_t)(base + node) * DIN + j] : 0.f;
    }
    __syncthreads();
    int ni = tid >> 2;
    int ko = (tid & 3) * 4;
    float a0 = bs[ko], a1 = bs[ko + 1], a2 = bs[ko + 2], a3 = bs[ko + 3];
#pragma unroll 8
    for (int j = 0; j < DIN; j++) {
        float xv = xs[ni][j];
        a0 += xv * ws[j][ko];
        a1 += xv * ws[j][ko + 1];
        a2 += xv * ws[j][ko + 2];
        a3 += xv * ws[j][ko + 3];
    }
    int node = base + ni;
    if (node < n) {
        float* h = (which == 0) ? g_hp : g_ht;
        *(float4*)(h + node * HID + ko) = make_float4(a0, a1, a2, a3);
    }
}

// ---------------- per-node attention dots: 4 dots per node ----------------
__global__ __launch_bounds__(256) void dots_kernel(
    int which,
    const float* __restrict__ a0, const float* __restrict__ a1,
    const float* __restrict__ a2, const float* __restrict__ a3, int n)
{
    __shared__ float sa[4][HID];
    int tid = threadIdx.x;
    if (tid < 4 * HID) {
        const float* src = (tid < 16) ? a0 : (tid < 32) ? a1 : (tid < 48) ? a2 : a3;
        sa[tid / HID][tid % HID] = src[tid % HID];
    }
    __syncthreads();
    int i = blockIdx.x * blockDim.x + tid;
    if (i >= n) return;
    const float* h = (which == 0) ? g_hp : g_ht;
    float hh[HID];
    const float4* hv = (const float4*)(h + i * HID);
#pragma unroll
    for (int c = 0; c < 4; c++) {
        float4 v = hv[c];
        hh[4 * c + 0] = v.x; hh[4 * c + 1] = v.y; hh[4 * c + 2] = v.z; hh[4 * c + 3] = v.w;
    }
    float d0 = 0.f, d1 = 0.f, d2 = 0.f, d3 = 0.f;
#pragma unroll
    for (int k = 0; k < HID; k++) {
        d0 += hh[k] * sa[0][k];
        d1 += hh[k] * sa[1][k];
        d2 += hh[k] * sa[2][k];
        d3 += hh[k] * sa[3][k];
    }
    if (which == 0) {        // from hp
        g_a_pt_src[i] = d0;  // hp . a_src_pt
        g_a_tp_dst[i] = d1;  // hp . a_dst_tp
        g_a_pp_src[i] = d2;  // hp . a_src_pp
        g_a_pp_dst[i] = d3;  // hp . a_dst_pp
    } else {                 // from ht
        g_a_pt_dst[i] = d0;  // ht . a_dst_pt
        g_a_tt_src[i] = d1;  // ht . a_src_tt
        g_a_tt_dst[i] = d2;  // ht . a_dst_tt
        g_a_tp_src[i] = d3;  // ht . a_src_tp
    }
}

// ---------------- fused edge pass ----------------
// s[dst] += e;  out[dst] += e * h_src[src]   where e = exp(leaky_relu(alpha)).
// Normalization deferred to the per-node tail, so the two scatters are independent
// and can share one read of the edge index + one alpha gather.
__global__ __launch_bounds__(256) void edge_fused(
    const int* __restrict__ src, const int* __restrict__ dst, int E, int type)
{
    int i = blockIdx.x * blockDim.x + threadIdx.x;
    if (i >= E) return;
    const float *asrc, *adst, *h;
    float *s, *out;
    switch (type) {
        case 0: asrc = g_a_pt_src; adst = g_a_pt_dst; h = g_hp; s = g_s_pt; out = g_out_pt; break;
        case 1: asrc = g_a_tt_src; adst = g_a_tt_dst; h = g_ht; s = g_s_tt; out = g_out_tt; break;
        case 2: asrc = g_a_tp_src; adst = g_a_tp_dst; h = g_ht; s = g_s_tp; out = g_out_tp; break;
        default: asrc = g_a_pp_src; adst = g_a_pp_dst; h = g_hp; s = g_s_pp; out = g_out_pp; break;
    }
    int si = src[i], di = dst[i];
    float a = __ldg(asrc + si) + __ldg(adst + di);
    a = (a > 0.f) ? a : 0.2f * a;
    float e = __expf(a);
    red_add_f32(s + di, e);
    const float4* hv = (const float4*)(h + si * HID);
    float* ob = out + di * HID;
#pragma unroll
    for (int c = 0; c < 4; c++) {
        float4 v = hv[c];
        red_add_v4(ob + c * 4, e * v.x, e * v.y, e * v.z, e * v.w);
    }
}

// ---------------- semantic reduce: S[m][k] = sum_n tanh((relu(out_m/s_m) @ K + b)[k]) ----------------
__global__ __launch_bounds__(256) void sem_reduce_kernel(
    const float* __restrict__ kw, const float* __restrict__ kb, int which, int n)
{
    __shared__ float ksm[HID * HID];
    __shared__ float kbs[HID];
    __shared__ float acc[2 * HID];
    int tid = threadIdx.x;
    if (tid < HID * HID) ksm[tid] = kw[tid];
    if (tid < HID) kbs[tid] = kb[tid];
    if (tid < 2 * HID) acc[tid] = 0.f;
    __syncthreads();

    const float *out0, *s0, *out1, *s1;
    if (which == 0) { out0 = g_out_tp; s0 = g_s_tp; out1 = g_out_pp; s1 = g_s_pp; }
    else            { out0 = g_out_pt; s0 = g_s_pt; out1 = g_out_tt; s1 = g_s_tt; }

    int i = blockIdx.x * blockDim.x + tid;
    float v0[HID], v1[HID];
    if (i < n) {
        float inv0 = 1.f / (s0[i] + 1e-16f);
        float inv1 = 1.f / (s1[i] + 1e-16f);
        float z0[HID], z1[HID];
        const float4* o0 = (const float4*)(out0 + i * HID);
        const float4* o1 = (const float4*)(out1 + i * HID);
#pragma unroll
        for (int c = 0; c < 4; c++) {
            float4 a = o0[c], b = o1[c];
            z0[4 * c + 0] = fmaxf(a.x * inv0, 0.f); z0[4 * c + 1] = fmaxf(a.y * inv0, 0.f);
            z0[4 * c + 2] = fmaxf(a.z * inv0, 0.f); z0[4 * c + 3] = fmaxf(a.w * inv0, 0.f);
            z1[4 * c + 0] = fmaxf(b.x * inv1, 0.f); z1[4 * c + 1] = fmaxf(b.y * inv1, 0.f);
            z1[4 * c + 2] = fmaxf(b.z * inv1, 0.f); z1[4 * c + 3] = fmaxf(b.w * inv1, 0.f);
        }
#pragma unroll
        for (int k = 0; k < HID; k++) {
            float d0 = kbs[k], d1 = kbs[k];
#pragma unroll
            for (int j = 0; j < HID; j++) {
                float kk = ksm[j * HID + k];
                d0 += z0[j] * kk;
                d1 += z1[j] * kk;
            }
            v0[k] = tanhf(d0);
            v1[k] = tanhf(d1);
        }
    } else {
#pragma unroll
        for (int k = 0; k < HID; k++) { v0[k] = 0.f; v1[k] = 0.f; }
    }
    // warp butterfly reduce all 32 components
#pragma unroll
    for (int k = 0; k < HID; k++) {
#pragma unroll
        for (int off = 16; off > 0; off >>= 1) {
            v0[k] += __shfl_xor_sync(0xffffffffu, v0[k], off);
            v1[k] += __shfl_xor_sync(0xffffffffu, v1[k], off);
        }
    }
    if ((tid & 31) == 0) {
#pragma unroll
        for (int k = 0; k < HID; k++) {
            atomicAdd(&acc[k], v0[k]);
            atomicAdd(&acc[HID + k], v1[k]);
        }
    }
    __syncthreads();
    float* S = (which == 0) ? g_S_p : g_S_t;
    if (tid < 2 * HID) atomicAdd(&S[tid], acc[tid]);
}

// ---------------- semantic attention softmax (tiny) ----------------
__global__ void attn_kernel(const float* __restrict__ q, int n) {
    float invn = 1.f / (float)n;
    float sc[4];
    for (int m = 0; m < 2; m++) {
        float sp = 0.f, st = 0.f;
        for (int k = 0; k < HID; k++) {
            sp += q[k] * g_S_p[m * HID + k];
            st += q[k] * g_S_t[m * HID + k];
        }
        sc[m] = sp * invn;
        sc[2 + m] = st * invn;
    }
    {   // p softmax
        float m = fmaxf(sc[0], sc[1]);
        float e0 = __expf(sc[0] - m), e1 = __expf(sc[1] - m);
        g_attn[0] = e0 / (e0 + e1);
        g_attn[1] = e1 / (e0 + e1);
    }
    {   // t softmax
        float m = fmaxf(sc[2], sc[3]);
        float e0 = __expf(sc[2] - m), e1 = __expf(sc[3] - m);
        g_attn[2] = e0 / (e0 + e1);
        g_attn[3] = e1 / (e0 + e1);
    }
}

// ---------------- pooled[k] += sum_n relu(attn0*z0 + attn1*z1)[k] ----------------
__global__ __launch_bounds__(256) void pool_kernel(int which, int n) {
    __shared__ float acc[HID];
    int tid = threadIdx.x;
    if (tid < HID) acc[tid] = 0.f;
    __syncthreads();

    const float *out0, *s0, *out1, *s1;
    float a0, a1;
    if (which == 0) {
        out0 = g_out_tp; s0 = g_s_tp; out1 = g_out_pp; s1 = g_s_pp;
        a0 = g_attn[0]; a1 = g_attn[1];
    } else {
        out0 = g_out_pt; s0 = g_s_pt; out1 = g_out_tt; s1 = g_s_tt;
        a0 = g_attn[2]; a1 = g_attn[3];
    }
    int i = blockIdx.x * blockDim.x + tid;
    float p[HID];
    if (i < n) {
        float inv0 = 1.f / (s0[i] + 1e-16f);
        float inv1 = 1.f / (s1[i] + 1e-16f);
        const float4* o0 = (const float4*)(out0 + i * HID);
        const float4* o1 = (const float4*)(out1 + i * HID);
#pragma unroll
        for (int c = 0; c < 4; c++) {
            float4 a = o0[c], b = o1[c];
            float z;
            z = a0 * fmaxf(a.x * inv0, 0.f) + a1 * fmaxf(b.x * inv1, 0.f); p[4*c+0] = fmaxf(z, 0.f);
            z = a0 * fmaxf(a.y * inv0, 0.f) + a1 * fmaxf(b.y * inv1, 0.f); p[4*c+1] = fmaxf(z, 0.f);
            z = a0 * fmaxf(a.z * inv0, 0.f) + a1 * fmaxf(b.z * inv1, 0.f); p[4*c+2] = fmaxf(z, 0.f);
            z = a0 * fmaxf(a.w * inv0, 0.f) + a1 * fmaxf(b.w * inv1, 0.f); p[4*c+3] = fmaxf(z, 0.f);
        }
    } else {
#pragma unroll
        for (int k = 0; k < HID; k++) p[k] = 0.f;
    }
#pragma unroll
    for (int k = 0; k < HID; k++) {
#pragma unroll
        for (int off = 16; off > 0; off >>= 1)
            p[k] += __shfl_xor_sync(0xffffffffu, p[k], off);
    }
    if ((tid & 31) == 0) {
#pragma unroll
        for (int k = 0; k < HID; k++) atomicAdd(&acc[k], p[k]);
    }
    __syncthreads();
    if (tid < HID) atomicAdd(&g_pooled[tid], acc[tid]);
}

// ---------------- final linear ----------------
__global__ void final_kernel(const float* __restrict__ lw, const float* __restrict__ lb,
                             float* __restrict__ out) {
    float r = lb[0];
    for (int k = 0; k < HID; k++) r += g_pooled[k] * lw[k];
    out[0] = r;
}

// ---------------- launch ----------------
extern "C" void kernel_launch(void* const* d_in, const int* in_sizes, int n_in,
                              void* d_out, int out_size)
{
    const float* x_place  = (const float*)d_in[0];
    const float* x_trans  = (const float*)d_in[1];
    const float* w_p      = (const float*)d_in[2];
    const float* b_p      = (const float*)d_in[3];
    const float* w_t      = (const float*)d_in[4];
    const float* b_t      = (const float*)d_in[5];
    const float* a_src_pt = (const float*)d_in[6];
    const float* a_dst_pt = (const float*)d_in[7];
    const float* a_src_tp = (const float*)d_in[8];
    const float* a_dst_tp = (const float*)d_in[9];
    const float* a_src_pp = (const float*)d_in[10];
    const float* a_dst_pp = (const float*)d_in[11];
    const float* a_src_tt = (const float*)d_in[12];
    const float* a_dst_tt = (const float*)d_in[13];
    const float* q        = (const float*)d_in[14];
    const float* k_w      = (const float*)d_in[15];
    const float* k_b      = (const float*)d_in[16];
    const float* lin_w    = (const float*)d_in[17];
    const float* lin_b    = (const float*)d_in[18];
    const int* e_pt = (const int*)d_in[19];
    const int* e_tp = (const int*)d_in[20];
    const int* e_pp = (const int*)d_in[21];
    const int* e_tt = (const int*)d_in[22];

    int N    = in_sizes[0] / DIN;
    int E_pt = in_sizes[19] / 2;
    int E_tp = in_sizes[20] / 2;
    int E_pp = in_sizes[21] / 2;
    int E_tt = in_sizes[22] / 2;

    int nz = N * HID;
    zero_kernel<<<(nz + 255) / 256, 256>>>(N);

    int pb = (N + 63) / 64;
    proj_kernel<<<pb, 256>>>(x_place, w_p, b_p, 0, N);
    proj_kernel<<<pb, 256>>>(x_trans, w_t, b_t, 1, N);

    int nb = (N + 255) / 256;
    dots_kernel<<<nb, 256>>>(0, a_src_pt, a_dst_tp, a_src_pp, a_dst_pp, N);
    dots_kernel<<<nb, 256>>>(1, a_dst_pt, a_src_tt, a_dst_tt, a_src_tp, N);

    // fused edge pass: denominator + weighted aggregation in one sweep
    edge_fused<<<(E_pt + 255) / 256, 256>>>(e_pt, e_pt + E_pt, E_pt, 0);
    edge_fused<<<(E_tt + 255) / 256, 256>>>(e_tt, e_tt + E_tt, E_tt, 1);
    edge_fused<<<(E_tp + 255) / 256, 256>>>(e_tp, e_tp + E_tp, E_tp, 2);
    edge_fused<<<(E_pp + 255) / 256, 256>>>(e_pp, e_pp + E_pp, E_pp, 3);

    // semantic attention
    sem_reduce_kernel<<<nb, 256>>>(k_w, k_b, 0, N);
    sem_reduce_kernel<<<nb, 256>>>(k_w, k_b, 1, N);
    attn_kernel<<<1, 1>>>(q, N);
    pool_kernel<<<nb, 256>>>(0, N);
    pool_kernel<<<nb, 256>>>(1, N);
    final_kernel<<<1, 1>>>(lin_w, lin_b, (float*)d_out);
}

// round 4
// speedup vs baseline: 1.5096x; 1.5096x over previous
#include <cuda_runtime.h>
#include <cuda_fp16.h>

typedef unsigned int u32;

#define DIN 128
#define HID 16
#define NMAX 100000

// ---------------- device scratch (static; no runtime allocation) ----------------
__device__ __align__(16) float g_hp[NMAX * HID];
__device__ __align__(16) float g_ht[NMAX * HID];
// fp16 copies of h for the edge-scatter payload (32 B/row)
__device__ __align__(16) __half g_hp_h[NMAX * HID];
__device__ __align__(16) __half g_ht_h[NMAX * HID];

// per-node attention dot products, one pair per edge type
__device__ float g_a_pt_src[NMAX], g_a_pt_dst[NMAX];
__device__ float g_a_tt_src[NMAX], g_a_tt_dst[NMAX];
__device__ float g_a_tp_src[NMAX], g_a_tp_dst[NMAX];
__device__ float g_a_pp_src[NMAX], g_a_pp_dst[NMAX];

// softmax denominators per edge type (unshifted, f32)
__device__ float g_s_pt[NMAX], g_s_tt[NMAX], g_s_tp[NMAX], g_s_pp[NMAX];

// UN-normalized aggregation outputs per edge type (fp16 accumulators)
__device__ __align__(16) __half g_out_pt[NMAX * HID];
__device__ __align__(16) __half g_out_tt[NMAX * HID];
__device__ __align__(16) __half g_out_tp[NMAX * HID];
__device__ __align__(16) __half g_out_pp[NMAX * HID];

// semantic-attention accumulators
__device__ float g_S_p[2 * HID];
__device__ float g_S_t[2 * HID];
__device__ float g_attn[4];     // [attn_p0, attn_p1, attn_t0, attn_t1]
__device__ float g_pooled[HID];

// ---------------- helpers ----------------
__device__ __forceinline__ void red_add_f32(float* addr, float v) {
    asm volatile("red.global.add.f32 [%0], %1;" :: "l"(addr), "f"(v) : "memory");
}
// vector fp16x2 reduction: 8 halves per op
__device__ __forceinline__ void red_add_v4h2(__half* addr, u32 a, u32 b, u32 c, u32 d) {
    asm volatile("red.global.add.noftz.v4.f16x2 [%0], {%1, %2, %3, %4};"
                 :: "l"(addr), "r"(a), "r"(b), "r"(c), "r"(d) : "memory");
}
__device__ __forceinline__ u32 hmul2u(u32 a, u32 e2) {
    __half2 r = __hmul2(*(__half2*)&a, *(__half2*)&e2);
    return *(u32*)&r;
}
__device__ __forceinline__ float2 h2f(u32 u) {
    return __half22float2(*(__half2*)&u);
}

// ---------------- zero scratch ----------------
__global__ void zero_kernel(int n) {
    int i = blockIdx.x * blockDim.x + threadIdx.x;
    int n8 = n * (HID / 2);   // out arrays as u32 (half2) elements
    if (i < n8) {
        ((u32*)g_out_pt)[i] = 0u; ((u32*)g_out_tt)[i] = 0u;
        ((u32*)g_out_tp)[i] = 0u; ((u32*)g_out_pp)[i] = 0u;
    }
    if (i < n) {
        g_s_pt[i] = 0.f; g_s_tt[i] = 0.f; g_s_tp[i] = 0.f; g_s_pp[i] = 0.f;
    }
    if (i < 2 * HID) { g_S_p[i] = 0.f; g_S_t[i] = 0.f; }
    if (i < HID) g_pooled[i] = 0.f;
}

// ---------------- projection: h = x @ W + b (writes f32 + fp16 copies) ----------------
__global__ __launch_bounds__(256) void proj_kernel(
    const float* __restrict__ x, const float* __restrict__ w,
    const float* __restrict__ b, int which, int n)
{
    __shared__ float xs[64][DIN + 4];
    __shared__ float ws[DIN][HID];
    __shared__ float bs[HID];
    int tid = threadIdx.x;
    for (int idx = tid; idx < DIN * HID; idx += 256)
        ws[idx / HID][idx % HID] = w[idx];
    if (tid < HID) bs[tid] = b[tid];
    int base = blockIdx.x * 64;
    for (int l = tid; l < 64 * DIN; l += 256) {
        int node = l / DIN, j = l % DIN;
        xs[node][j] = (base + node < n) ? x[(size_t)(base + node) * DIN + j] : 0.f;
    }
    __syncthreads();
    int ni = tid >> 2;
    int ko = (tid & 3) * 4;
    float a0 = bs[ko], a1 = bs[ko + 1], a2 = bs[ko + 2], a3 = bs[ko + 3];
#pragma unroll 8
    for (int j = 0; j < DIN; j++) {
        float xv = xs[ni][j];
        a0 += xv * ws[j][ko];
        a1 += xv * ws[j][ko + 1];
        a2 += xv * ws[j][ko + 2];
        a3 += xv * ws[j][ko + 3];
    }
    int node = base + ni;
    if (node < n) {
        float* h = (which == 0) ? g_hp : g_ht;
        __half* hh = (which == 0) ? g_hp_h : g_ht_h;
        *(float4*)(h + node * HID + ko) = make_float4(a0, a1, a2, a3);
        __half2 p0 = __floats2half2_rn(a0, a1);
        __half2 p1 = __floats2half2_rn(a2, a3);
        uint2 pk;
        pk.x = *(u32*)&p0;
        pk.y = *(u32*)&p1;
        *(uint2*)(hh + node * HID + ko) = pk;
    }
}

// ---------------- per-node attention dots: 4 dots per node ----------------
__global__ __launch_bounds__(256) void dots_kernel(
    int which,
    const float* __restrict__ a0, const float* __restrict__ a1,
    const float* __restrict__ a2, const float* __restrict__ a3, int n)
{
    __shared__ float sa[4][HID];
    int tid = threadIdx.x;
    if (tid < 4 * HID) {
        const float* src = (tid < 16) ? a0 : (tid < 32) ? a1 : (tid < 48) ? a2 : a3;
        sa[tid / HID][tid % HID] = src[tid % HID];
    }
    __syncthreads();
    int i = blockIdx.x * blockDim.x + tid;
    if (i >= n) return;
    const float* h = (which == 0) ? g_hp : g_ht;
    float hh[HID];
    const float4* hv = (const float4*)(h + i * HID);
#pragma unroll
    for (int c = 0; c < 4; c++) {
        float4 v = hv[c];
        hh[4 * c + 0] = v.x; hh[4 * c + 1] = v.y; hh[4 * c + 2] = v.z; hh[4 * c + 3] = v.w;
    }
    float d0 = 0.f, d1 = 0.f, d2 = 0.f, d3 = 0.f;
#pragma unroll
    for (int k = 0; k < HID; k++) {
        d0 += hh[k] * sa[0][k];
        d1 += hh[k] * sa[1][k];
        d2 += hh[k] * sa[2][k];
        d3 += hh[k] * sa[3][k];
    }
    if (which == 0) {        // from hp
        g_a_pt_src[i] = d0;  // hp . a_src_pt
        g_a_tp_dst[i] = d1;  // hp . a_dst_tp
        g_a_pp_src[i] = d2;  // hp . a_src_pp
        g_a_pp_dst[i] = d3;  // hp . a_dst_pp
    } else {                 // from ht
        g_a_pt_dst[i] = d0;  // ht . a_dst_pt
        g_a_tt_src[i] = d1;  // ht . a_src_tt
        g_a_tt_dst[i] = d2;  // ht . a_dst_tt
        g_a_tp_src[i] = d3;  // ht . a_src_tp
    }
}

// ---------------- fused edge pass, all 4 types in one launch ----------------
// type = blockIdx.y: 0=pt, 1=tt, 2=tp, 3=pp
// s[dst] += e (f32);  out[dst] += e * h_src[src] (fp16, 2 vector REDs)
__global__ __launch_bounds__(256) void edge_fused(
    const int* __restrict__ e_pt, const int* __restrict__ e_tt,
    const int* __restrict__ e_tp, const int* __restrict__ e_pp,
    int E_pt, int E_tt, int E_tp, int E_pp)
{
    int type = blockIdx.y;
    const int* e; int E;
    const float *asrc, *adst;
    const __half* h;
    float* s; __half* out;
    switch (type) {
        case 0:  e = e_pt; E = E_pt; asrc = g_a_pt_src; adst = g_a_pt_dst;
                 h = g_hp_h; s = g_s_pt; out = g_out_pt; break;
        case 1:  e = e_tt; E = E_tt; asrc = g_a_tt_src; adst = g_a_tt_dst;
                 h = g_ht_h; s = g_s_tt; out = g_out_tt; break;
        case 2:  e = e_tp; E = E_tp; asrc = g_a_tp_src; adst = g_a_tp_dst;
                 h = g_ht_h; s = g_s_tp; out = g_out_tp; break;
        default: e = e_pp; E = E_pp; asrc = g_a_pp_src; adst = g_a_pp_dst;
                 h = g_hp_h; s = g_s_pp; out = g_out_pp; break;
    }
    int i = blockIdx.x * blockDim.x + threadIdx.x;
    if (i >= E) return;
    int si = __ldg(e + i), di = __ldg(e + E + i);
    float a = __ldg(asrc + si) + __ldg(adst + di);
    a = (a > 0.f) ? a : 0.2f * a;
    float ef = __expf(a);
    red_add_f32(s + di, ef);
    __half2 e2h = __float2half2_rn(ef);
    u32 e2 = *(u32*)&e2h;
    const uint4* hv = (const uint4*)(h + (size_t)si * HID);
    uint4 r0 = __ldg(hv);       // halves 0..7
    uint4 r1 = __ldg(hv + 1);   // halves 8..15
    __half* ob = out + (size_t)di * HID;
    red_add_v4h2(ob,     hmul2u(r0.x, e2), hmul2u(r0.y, e2),
                          hmul2u(r0.z, e2), hmul2u(r0.w, e2));
    red_add_v4h2(ob + 8, hmul2u(r1.x, e2), hmul2u(r1.y, e2),
                          hmul2u(r1.z, e2), hmul2u(r1.w, e2));
}

// ---------------- semantic reduce: S[m][k] = sum_n tanh((relu(out_m/s_m) @ K + b)[k]) ----------------
__global__ __launch_bounds__(256) void sem_reduce_kernel(
    const float* __restrict__ kw, const float* __restrict__ kb, int which, int n)
{
    __shared__ float ksm[HID * HID];
    __shared__ float kbs[HID];
    __shared__ float acc[2 * HID];
    int tid = threadIdx.x;
    if (tid < HID * HID) ksm[tid] = kw[tid];
    if (tid < HID) kbs[tid] = kb[tid];
    if (tid < 2 * HID) acc[tid] = 0.f;
    __syncthreads();

    const __half *out0, *out1;
    const float *s0, *s1;
    if (which == 0) { out0 = g_out_tp; s0 = g_s_tp; out1 = g_out_pp; s1 = g_s_pp; }
    else            { out0 = g_out_pt; s0 = g_s_pt; out1 = g_out_tt; s1 = g_s_tt; }

    int i = blockIdx.x * blockDim.x + tid;
    float v0[HID], v1[HID];
    if (i < n) {
        float inv0 = 1.f / (s0[i] + 1e-16f);
        float inv1 = 1.f / (s1[i] + 1e-16f);
        float z0[HID], z1[HID];
        const uint4* o0 = (const uint4*)(out0 + (size_t)i * HID);
        const uint4* o1 = (const uint4*)(out1 + (size_t)i * HID);
#pragma unroll
        for (int c = 0; c < 2; c++) {
            uint4 a = o0[c], b = o1[c];
            float2 f;
            f = h2f(a.x); z0[8*c+0] = fmaxf(f.x*inv0,0.f); z0[8*c+1] = fmaxf(f.y*inv0,0.f);
            f = h2f(a.y); z0[8*c+2] = fmaxf(f.x*inv0,0.f); z0[8*c+3] = fmaxf(f.y*inv0,0.f);
            f = h2f(a.z); z0[8*c+4] = fmaxf(f.x*inv0,0.f); z0[8*c+5] = fmaxf(f.y*inv0,0.f);
            f = h2f(a.w); z0[8*c+6] = fmaxf(f.x*inv0,0.f); z0[8*c+7] = fmaxf(f.y*inv0,0.f);
            f = h2f(b.x); z1[8*c+0] = fmaxf(f.x*inv1,0.f); z1[8*c+1] = fmaxf(f.y*inv1,0.f);
            f = h2f(b.y); z1[8*c+2] = fmaxf(f.x*inv1,0.f); z1[8*c+3] = fmaxf(f.y*inv1,0.f);
            f = h2f(b.z); z1[8*c+4] = fmaxf(f.x*inv1,0.f); z1[8*c+5] = fmaxf(f.y*inv1,0.f);
            f = h2f(b.w); z1[8*c+6] = fmaxf(f.x*inv1,0.f); z1[8*c+7] = fmaxf(f.y*inv1,0.f);
        }
#pragma unroll
        for (int k = 0; k < HID; k++) {
            float d0 = kbs[k], d1 = kbs[k];
#pragma unroll
            for (int j = 0; j < HID; j++) {
                float kk = ksm[j * HID + k];
                d0 += z0[j] * kk;
                d1 += z1[j] * kk;
            }
            v0[k] = tanhf(d0);
            v1[k] = tanhf(d1);
        }
    } else {
#pragma unroll
        for (int k = 0; k < HID; k++) { v0[k] = 0.f; v1[k] = 0.f; }
    }
#pragma unroll
    for (int k = 0; k < HID; k++) {
#pragma unroll
        for (int off = 16; off > 0; off >>= 1) {
            v0[k] += __shfl_xor_sync(0xffffffffu, v0[k], off);
            v1[k] += __shfl_xor_sync(0xffffffffu, v1[k], off);
        }
    }
    if ((tid & 31) == 0) {
#pragma unroll
        for (int k = 0; k < HID; k++) {
            atomicAdd(&acc[k], v0[k]);
            atomicAdd(&acc[HID + k], v1[k]);
        }
    }
    __syncthreads();
    float* S = (which == 0) ? g_S_p : g_S_t;
    if (tid < 2 * HID) atomicAdd(&S[tid], acc[tid]);
}

// ---------------- semantic attention softmax (tiny) ----------------
__global__ void attn_kernel(const float* __restrict__ q, int n) {
    float invn = 1.f / (float)n;
    float sc[4];
    for (int m = 0; m < 2; m++) {
        float sp = 0.f, st = 0.f;
        for (int k = 0; k < HID; k++) {
            sp += q[k] * g_S_p[m * HID + k];
            st += q[k] * g_S_t[m * HID + k];
        }
        sc[m] = sp * invn;
        sc[2 + m] = st * invn;
    }
    {
        float m = fmaxf(sc[0], sc[1]);
        float e0 = __expf(sc[0] - m), e1 = __expf(sc[1] - m);
        g_attn[0] = e0 / (e0 + e1);
        g_attn[1] = e1 / (e0 + e1);
    }
    {
        float m = fmaxf(sc[2], sc[3]);
        float e0 = __expf(sc[2] - m), e1 = __expf(sc[3] - m);
        g_attn[2] = e0 / (e0 + e1);
        g_attn[3] = e1 / (e0 + e1);
    }
}

// ---------------- pooled[k] += sum_n relu(attn0*z0 + attn1*z1)[k] ----------------
__global__ __launch_bounds__(256) void pool_kernel(int which, int n) {
    __shared__ float acc[HID];
    int tid = threadIdx.x;
    if (tid < HID) acc[tid] = 0.f;
    __syncthreads();

    const __half *out0, *out1;
    const float *s0, *s1;
    float a0, a1;
    if (which == 0) {
        out0 = g_out_tp; s0 = g_s_tp; out1 = g_out_pp; s1 = g_s_pp;
        a0 = g_attn[0]; a1 = g_attn[1];
    } else {
        out0 = g_out_pt; s0 = g_s_pt; out1 = g_out_tt; s1 = g_s_tt;
        a0 = g_attn[2]; a1 = g_attn[3];
    }
    int i = blockIdx.x * blockDim.x + tid;
    float p[HID];
    if (i < n) {
        float inv0 = 1.f / (s0[i] + 1e-16f);
        float inv1 = 1.f / (s1[i] + 1e-16f);
        const uint4* o0 = (const uint4*)(out0 + (size_t)i * HID);
        const uint4* o1 = (const uint4*)(out1 + (size_t)i * HID);
#pragma unroll
        for (int c = 0; c < 2; c++) {
            uint4 a = o0[c], b = o1[c];
            u32 au[4]; au[0] = a.x; au[1] = a.y; au[2] = a.z; au[3] = a.w;
            u32 bu[4]; bu[0] = b.x; bu[1] = b.y; bu[2] = b.z; bu[3] = b.w;
#pragma unroll
            for (int j = 0; j < 4; j++) {
                float2 fa = h2f(au[j]);
                float2 fb = h2f(bu[j]);
                float z;
                z = a0 * fmaxf(fa.x * inv0, 0.f) + a1 * fmaxf(fb.x * inv1, 0.f);
                p[8*c + 2*j + 0] = fmaxf(z, 0.f);
                z = a0 * fmaxf(fa.y * inv0, 0.f) + a1 * fmaxf(fb.y * inv1, 0.f);
                p[8*c + 2*j + 1] = fmaxf(z, 0.f);
            }
        }
    } else {
#pragma unroll
        for (int k = 0; k < HID; k++) p[k] = 0.f;
    }
#pragma unroll
    for (int k = 0; k < HID; k++) {
#pragma unroll
        for (int off = 16; off > 0; off >>= 1)
            p[k] += __shfl_xor_sync(0xffffffffu, p[k], off);
    }
    if ((tid & 31) == 0) {
#pragma unroll
        for (int k = 0; k < HID; k++) atomicAdd(&acc[k], p[k]);
    }
    __syncthreads();
    if (tid < HID) atomicAdd(&g_pooled[tid], acc[tid]);
}

// ---------------- final linear ----------------
__global__ void final_kernel(const float* __restrict__ lw, const float* __restrict__ lb,
                             float* __restrict__ out) {
    float r = lb[0];
    for (int k = 0; k < HID; k++) r += g_pooled[k] * lw[k];
    out[0] = r;
}

// ---------------- launch ----------------
extern "C" void kernel_launch(void* const* d_in, const int* in_sizes, int n_in,
                              void* d_out, int out_size)
{
    const float* x_place  = (const float*)d_in[0];
    const float* x_trans  = (const float*)d_in[1];
    const float* w_p      = (const float*)d_in[2];
    const float* b_p      = (const float*)d_in[3];
    const float* w_t      = (const float*)d_in[4];
    const float* b_t      = (const float*)d_in[5];
    const float* a_src_pt = (const float*)d_in[6];
    const float* a_dst_pt = (const float*)d_in[7];
    const float* a_src_tp = (const float*)d_in[8];
    const float* a_dst_tp = (const float*)d_in[9];
    const float* a_src_pp = (const float*)d_in[10];
    const float* a_dst_pp = (const float*)d_in[11];
    const float* a_src_tt = (const float*)d_in[12];
    const float* a_dst_tt = (const float*)d_in[13];
    const float* q        = (const float*)d_in[14];
    const float* k_w      = (const float*)d_in[15];
    const float* k_b      = (const float*)d_in[16];
    const float* lin_w    = (const float*)d_in[17];
    const float* lin_b    = (const float*)d_in[18];
    const int* e_pt = (const int*)d_in[19];
    const int* e_tp = (const int*)d_in[20];
    const int* e_pp = (const int*)d_in[21];
    const int* e_tt = (const int*)d_in[22];

    int N    = in_sizes[0] / DIN;
    int E_pt = in_sizes[19] / 2;
    int E_tp = in_sizes[20] / 2;
    int E_pp = in_sizes[21] / 2;
    int E_tt = in_sizes[22] / 2;

    int nz = N * HID;       // covers n*8 (out half2 words) and n
    zero_kernel<<<(nz + 255) / 256, 256>>>(N);

    int pb = (N + 63) / 64;
    proj_kernel<<<pb, 256>>>(x_place, w_p, b_p, 0, N);
    proj_kernel<<<pb, 256>>>(x_trans, w_t, b_t, 1, N);

    int nb = (N + 255) / 256;
    dots_kernel<<<nb, 256>>>(0, a_src_pt, a_dst_tp, a_src_pp, a_dst_pp, N);
    dots_kernel<<<nb, 256>>>(1, a_dst_pt, a_src_tt, a_dst_tt, a_src_tp, N);

    // fused edge pass, all 4 types in one grid
    int Emax = max(max(E_pt, E_tt), max(E_tp, E_pp));
    dim3 eg((Emax + 255) / 256, 4);
    edge_fused<<<eg, 256>>>(e_pt, e_tt, e_tp, e_pp, E_pt, E_tt, E_tp, E_pp);

    // semantic attention
    sem_reduce_kernel<<<nb, 256>>>(k_w, k_b, 0, N);
    sem_reduce_kernel<<<nb, 256>>>(k_w, k_b, 1, N);
    attn_kernel<<<1, 1>>>(q, N);
    pool_kernel<<<nb, 256>>>(0, N);
    pool_kernel<<<nb, 256>>>(1, N);
    final_kernel<<<1, 1>>>(lin_w, lin_b, (float*)d_out);
}